// round 14
// baseline (speedup 1.0000x reference)
#include <cuda_runtime.h>
#include <cuda_fp16.h>
#include <math.h>

#define NN 50000
#define EE 800000
#define RR 32
#define BB 15
#define HH 8
#define CC 16
#define WPADH 65   // half2 row stride for w2 smem

// ---- scratch (device globals; no allocation allowed) ----
__device__ __align__(16) int    g_counts[NN * RR];             // 6.4 MB (tgt,rel) counts
__device__ __align__(16) int    g_deg[NN];                     // per-target degree
__device__ __align__(16) int    g_off[NN + 1];                 // CSR offsets
__device__ __align__(16) int    g_cur[NN];                     // scatter cursors
__device__ __align__(16) int2   g_sorted[EE];                  // {src|et<<16, norm bits}
__device__ __align__(16) __half g_w1h[(size_t)RR * NN * HH];   // 25.6 MB fp16 table
__device__ __align__(16) float  g_w2[RR * HH * CC];            // 16 KB
__device__ __align__(16) float  g_agg1[NN * HH];               // pre-relu x (prebias root1+bias1)
__device__ __align__(16) float  g_agg2[NN * CC];               // layer-2 aggregate

// ---- 0. setup: zero counts/deg, pre-bias agg1, tiny w2 ----
__global__ void k_setup(const float* __restrict__ basis2,
                        const float* __restrict__ comp2,
                        const float* __restrict__ root1,
                        const float* __restrict__ bias1) {
    int i = blockIdx.x * blockDim.x + threadIdx.x;
    int stride = gridDim.x * blockDim.x;
    if (i < RR * HH * CC) {
        int r  = i / (HH * CC);
        int hc = i % (HH * CC);
        float s = 0.0f;
#pragma unroll
        for (int b = 0; b < BB; b++)
            s += comp2[r * BB + b] * basis2[b * (HH * CC) + hc];
        g_w2[i] = s;
    }
    int4 zi = make_int4(0, 0, 0, 0);
    for (int j = i; j < NN * RR / 4; j += stride) ((int4*)g_counts)[j] = zi;
    for (int j = i; j < NN / 4; j += stride) ((int4*)g_deg)[j] = zi;
    if (i < 2) g_deg[NN - 2 + i] = 0;   // NN%4==0 actually; harmless guard
    const float4* r4 = (const float4*)root1;
    float b0 = bias1[0], b1 = bias1[1], b2 = bias1[2], b3 = bias1[3];
    float b4v = bias1[4], b5 = bias1[5], b6 = bias1[6], b7 = bias1[7];
    for (int j = i; j < NN * HH / 4; j += stride) {
        float4 v = r4[j];
        if ((j & 1) == 0) { v.x += b0; v.y += b1; v.z += b2; v.w += b3; }
        else              { v.x += b4v; v.y += b5; v.z += b6; v.w += b7; }
        ((float4*)g_agg1)[j] = v;
    }
}

// ---- 1. FUSED: (tgt,rel) counts + per-tgt degree + fp16 w1 materialize ----
__global__ void k_cw1(const int* __restrict__ edge_index,
                      const int* __restrict__ edge_type,
                      const float* __restrict__ basis1,
                      const float* __restrict__ comp1) {
    __shared__ float sc[RR * BB];
    int p = blockIdx.x * blockDim.x + threadIdx.x;
    bool w1block = (blockIdx.x * blockDim.x) < (NN * HH / 4);
    if (w1block) {
        for (int i = threadIdx.x; i < RR * BB; i += blockDim.x) sc[i] = comp1[i];
        __syncthreads();
    }
    if (p < EE / 2) {
        int2 tgt = ((const int2*)(edge_index + EE))[p];
        int2 et  = ((const int2*)edge_type)[p];
        atomicAdd(&g_counts[tgt.x * RR + et.x], 1);
        atomicAdd(&g_counts[tgt.y * RR + et.y], 1);
        atomicAdd(&g_deg[tgt.x], 1);
        atomicAdd(&g_deg[tgt.y], 1);
    }
    if (p < NN * HH / 4) {
        const float4* b4 = (const float4*)basis1;
        float4 bv[BB];
#pragma unroll
        for (int b = 0; b < BB; b++) bv[b] = __ldg(&b4[b * (NN * HH / 4) + p]);
        uint2* w2p = (uint2*)g_w1h;
#pragma unroll 4
        for (int r = 0; r < RR; r++) {
            float4 s = make_float4(0.f, 0.f, 0.f, 0.f);
#pragma unroll
            for (int b = 0; b < BB; b++) {
                float c = sc[r * BB + b];
                s.x += c * bv[b].x; s.y += c * bv[b].y;
                s.z += c * bv[b].z; s.w += c * bv[b].w;
            }
            __half2 h0 = __floats2half2_rn(s.x, s.y);
            __half2 h1 = __floats2half2_rn(s.z, s.w);
            uint2 packed;
            packed.x = *(unsigned*)&h0;
            packed.y = *(unsigned*)&h1;
            w2p[(size_t)r * (NN * HH / 4) + p] = packed;
        }
    }
}

// ---- 2. single-block exclusive scan of g_deg -> g_off, g_cur ----
#define SCAN_T 1024
#define CHUNK  ((NN + SCAN_T - 1) / SCAN_T)   // 49
__global__ void k_scan() {
    __shared__ int ssum[SCAN_T];
    int t = threadIdx.x;
    int base = t * CHUNK;
    int s = 0;
    for (int k = 0; k < CHUNK; k++) {
        int idx = base + k;
        if (idx < NN) s += g_deg[idx];
    }
    ssum[t] = s;
    __syncthreads();
    for (int d = 1; d < SCAN_T; d <<= 1) {
        int v = (t >= d) ? ssum[t - d] : 0;
        __syncthreads();
        ssum[t] += v;
        __syncthreads();
    }
    int run = (t == 0) ? 0 : ssum[t - 1];
    for (int k = 0; k < CHUNK; k++) {
        int idx = base + k;
        if (idx < NN) {
            g_off[idx] = run;
            g_cur[idx] = run;
            run += g_deg[idx];
        }
    }
    if (t == SCAN_T - 1) g_off[NN] = run;
}

// ---- 3. scatter edges into CSR order, norm precomputed ----
__global__ void k_sort(const int* __restrict__ edge_index,
                       const int* __restrict__ edge_type) {
    int e = blockIdx.x * blockDim.x + threadIdx.x;
    if (e >= EE) return;
    int src = __ldg(&edge_index[e]);
    int tgt = __ldg(&edge_index[EE + e]);
    int et  = __ldg(&edge_type[e]);
    int slot = atomicAdd(&g_cur[tgt], 1);
    float cnt  = (float)g_counts[tgt * RR + et];
    float norm = 1.0f / fmaxf(cnt, 1.0f);
    int2 rec;
    rec.x = src | (et << 16);
    rec.y = __float_as_int(norm);
    g_sorted[rec.x >= 0 ? slot : slot] = rec;   // plain store
}

// ---- 4. segmented layer-1: 8 lanes (h) per target, no atomics ----
__global__ void k_s1s() {
    int g = blockIdx.x * blockDim.x + threadIdx.x;
    int lane = g & 7;
    int n = g >> 3;
    if (n >= NN) return;
    int o0 = g_off[n], o1 = g_off[n + 1];
    float sum = 0.0f;
    for (int i = o0; i < o1; i++) {
        int2 pr = __ldg(&g_sorted[i]);          // broadcast across 8 lanes
        int src = pr.x & 0xFFFF;
        int et  = pr.x >> 16;
        float norm = __int_as_float(pr.y);
        __half w = g_w1h[((size_t)et * NN + src) * HH + lane];  // 16B sector / 8 lanes
        sum += norm * __half2float(w);
    }
    g_agg1[n * HH + lane] += sum;               // coalesced, prebias already there
}

// ---- 5. segmented layer-2: 8 lanes (c-pair) per target, no atomics ----
__global__ void k_s2s() {
    __shared__ __half2 sw[RR * WPADH];
    for (int i = threadIdx.x; i < RR * HH * CC / 2; i += blockDim.x) {
        int r  = i / (HH * CC / 2);
        int p2 = i % (HH * CC / 2);             // h*8 + c2
        sw[r * WPADH + p2] = __floats2half2_rn(g_w2[r * HH * CC + p2 * 2],
                                               g_w2[r * HH * CC + p2 * 2 + 1]);
    }
    __syncthreads();
    int g = blockIdx.x * blockDim.x + threadIdx.x;
    int lane = g & 7;                           // c2 index 0..7
    int n = g >> 3;
    if (n >= NN) return;
    int o0 = g_off[n], o1 = g_off[n + 1];
    float2 acc = make_float2(0.f, 0.f);
    for (int i = o0; i < o1; i++) {
        int2 pr = __ldg(&g_sorted[i]);
        int src = pr.x & 0xFFFF;
        int et  = pr.x >> 16;
        float norm = __int_as_float(pr.y);
        float4 x0 = *(const float4*)&g_agg1[src * HH];        // broadcast row
        float4 x1 = *(const float4*)&g_agg1[src * HH + 4];
        float xv[HH] = {fmaxf(x0.x,0.f), fmaxf(x0.y,0.f), fmaxf(x0.z,0.f), fmaxf(x0.w,0.f),
                        fmaxf(x1.x,0.f), fmaxf(x1.y,0.f), fmaxf(x1.z,0.f), fmaxf(x1.w,0.f)};
        const __half2* w = &sw[et * WPADH];
        float sx = 0.f, sy = 0.f;
#pragma unroll
        for (int h = 0; h < HH; h++) {
            float2 wf = __half22float2(w[h * (CC / 2) + lane]);
            sx += xv[h] * wf.x;
            sy += xv[h] * wf.y;
        }
        acc.x += norm * sx;
        acc.y += norm * sy;
    }
    ((float2*)g_agg2)[n * (CC / 2) + lane] = acc;   // coalesced 64B/target
}

// ---- 6. out = log_softmax(agg2 + relu(agg1) @ root2 + bias2) ----
__global__ void k_final(const float* __restrict__ root2,
                        const float* __restrict__ bias2,
                        float* __restrict__ out) {
    __shared__ float sr[HH * CC];
    __shared__ float sb[CC];
    for (int i = threadIdx.x; i < HH * CC; i += blockDim.x) sr[i] = root2[i];
    if (threadIdx.x < CC) sb[threadIdx.x] = bias2[threadIdx.x];
    __syncthreads();
    int n = blockIdx.x * blockDim.x + threadIdx.x;
    if (n >= NN) return;
    float4 x0 = *(const float4*)&g_agg1[n * HH];
    float4 x1 = *(const float4*)&g_agg1[n * HH + 4];
    float xv[HH] = {fmaxf(x0.x,0.f), fmaxf(x0.y,0.f), fmaxf(x0.z,0.f), fmaxf(x0.w,0.f),
                    fmaxf(x1.x,0.f), fmaxf(x1.y,0.f), fmaxf(x1.z,0.f), fmaxf(x1.w,0.f)};
    float v[CC];
    float m = -INFINITY;
#pragma unroll
    for (int c = 0; c < CC; c++) {
        float s = g_agg2[n * CC + c] + sb[c];
#pragma unroll
        for (int h = 0; h < HH; h++) s += xv[h] * sr[h * CC + c];
        v[c] = s;
        m = fmaxf(m, s);
    }
    float sum = 0.0f;
#pragma unroll
    for (int c = 0; c < CC; c++) sum += __expf(v[c] - m);
    float lse = m + __logf(sum);
#pragma unroll
    for (int c = 0; c < CC; c++) out[n * CC + c] = v[c] - lse;
}

extern "C" void kernel_launch(void* const* d_in, const int* in_sizes, int n_in,
                              void* d_out, int out_size) {
    const int*   edge_index = (const int*)d_in[0];   // (2, E)
    const int*   edge_type  = (const int*)d_in[1];   // (E,)
    const float* basis1     = (const float*)d_in[2]; // (B, N, H)
    const float* comp1      = (const float*)d_in[3]; // (R, B)
    const float* root1      = (const float*)d_in[4]; // (N, H)
    const float* bias1      = (const float*)d_in[5]; // (H,)
    const float* basis2     = (const float*)d_in[6]; // (B, H, C)
    const float* comp2      = (const float*)d_in[7]; // (R, B)
    const float* root2      = (const float*)d_in[8]; // (H, C)
    const float* bias2      = (const float*)d_in[9]; // (C,)
    float* out = (float*)d_out;

    k_setup<<<2048, 256>>>(basis2, comp2, root1, bias1);               // idx 0
    k_cw1<<<(EE / 2 + 255) / 256, 256>>>(edge_index, edge_type,
                                         basis1, comp1);               // idx 1
    k_scan<<<1, SCAN_T>>>();                                           // idx 2
    k_sort<<<(EE + 255) / 256, 256>>>(edge_index, edge_type);          // idx 3 (profiled)
    k_s1s<<<(NN * HH + 255) / 256, 256>>>();                           // idx 4
    k_s2s<<<(NN * HH + 255) / 256, 256>>>();                           // idx 5
    k_final<<<(NN + 127) / 128, 128>>>(root2, bias2, out);             // idx 6
}

// round 15
// speedup vs baseline: 2.4000x; 2.4000x over previous
#include <cuda_runtime.h>
#include <cuda_fp16.h>
#include <math.h>

#define NN 50000
#define EE 800000
#define RR 32
#define BB 15
#define HH 8
#define CC 16
#define WPADH 65   // half2 row stride for w2 smem: et -> distinct banks (65 odd)

// ---- scratch (device globals; no allocation allowed) ----
__device__ __align__(16) int    g_counts[NN * RR];             // 6.4 MB
__device__ __align__(16) __half g_w1h[(size_t)RR * NN * HH];   // 25.6 MB (fp16 table)
__device__ __align__(16) float  g_w2[RR * HH * CC];            // 16 KB
__device__ __align__(16) float  g_norm[EE];                    // 3.2 MB
__device__ __align__(16) float  g_agg1[NN * HH];               // 1.6 MB (pre-relu x)
__device__ __align__(16) float  g_agg2[NN * CC];               // 3.2 MB

__device__ __forceinline__ void red_add_v4(float* addr, float a, float b,
                                           float c, float d) {
    asm volatile("red.global.add.v4.f32 [%0], {%1,%2,%3,%4};"
                 :: "l"(addr), "f"(a), "f"(b), "f"(c), "f"(d) : "memory");
}

// ---- 0. setup: zero counts/agg2, pre-bias agg1 with root1+bias1, tiny w2 ----
__global__ void k_setup(const float* __restrict__ basis2,
                        const float* __restrict__ comp2,
                        const float* __restrict__ root1,
                        const float* __restrict__ bias1) {
    int i = blockIdx.x * blockDim.x + threadIdx.x;
    int stride = gridDim.x * blockDim.x;
    if (i < RR * HH * CC) {           // w2[r,h,c] = sum_b comp2[r,b]*basis2[b,h,c]
        int r  = i / (HH * CC);
        int hc = i % (HH * CC);
        float s = 0.0f;
#pragma unroll
        for (int b = 0; b < BB; b++)
            s += comp2[r * BB + b] * basis2[b * (HH * CC) + hc];
        g_w2[i] = s;
    }
    float4 z4 = make_float4(0.f, 0.f, 0.f, 0.f);
    int4   zi = make_int4(0, 0, 0, 0);
    for (int j = i; j < NN * RR / 4; j += stride) ((int4*)g_counts)[j] = zi;
    for (int j = i; j < NN * CC / 4; j += stride) ((float4*)g_agg2)[j] = z4;
    const float4* r4 = (const float4*)root1;
    float b0 = bias1[0], b1 = bias1[1], b2 = bias1[2], b3 = bias1[3];
    float b4v = bias1[4], b5 = bias1[5], b6 = bias1[6], b7 = bias1[7];
    for (int j = i; j < NN * HH / 4; j += stride) {
        float4 v = r4[j];
        if ((j & 1) == 0) { v.x += b0; v.y += b1; v.z += b2; v.w += b3; }
        else              { v.x += b4v; v.y += b5; v.z += b6; v.w += b7; }
        ((float4*)g_agg1)[j] = v;
    }
}

// ---- 1. FUSED: counts (all threads) + fp16 w1 materialize (low ids) ----
__global__ void k_cw1(const int* __restrict__ edge_index,
                      const int* __restrict__ edge_type,
                      const float* __restrict__ basis1,
                      const float* __restrict__ comp1) {
    __shared__ float sc[RR * BB];
    int p = blockIdx.x * blockDim.x + threadIdx.x;
    bool w1block = (blockIdx.x * blockDim.x) < (NN * HH / 4);
    if (w1block) {
        for (int i = threadIdx.x; i < RR * BB; i += blockDim.x) sc[i] = comp1[i];
        __syncthreads();
    }
    if (p < EE / 2) {
        int2 tgt = ((const int2*)(edge_index + EE))[p];
        int2 et  = ((const int2*)edge_type)[p];
        atomicAdd(&g_counts[tgt.x * RR + et.x], 1);
        atomicAdd(&g_counts[tgt.y * RR + et.y], 1);
    }
    if (p < NN * HH / 4) {
        const float4* b4 = (const float4*)basis1;
        float4 bv[BB];
#pragma unroll
        for (int b = 0; b < BB; b++) bv[b] = __ldg(&b4[b * (NN * HH / 4) + p]);
        uint2* w2p = (uint2*)g_w1h;    // 4 halves per quad
#pragma unroll 4
        for (int r = 0; r < RR; r++) {
            float4 s = make_float4(0.f, 0.f, 0.f, 0.f);
#pragma unroll
            for (int b = 0; b < BB; b++) {
                float c = sc[r * BB + b];
                s.x += c * bv[b].x; s.y += c * bv[b].y;
                s.z += c * bv[b].z; s.w += c * bv[b].w;
            }
            __half2 h0 = __floats2half2_rn(s.x, s.y);
            __half2 h1 = __floats2half2_rn(s.z, s.w);
            uint2 packed;
            packed.x = *(unsigned*)&h0;
            packed.y = *(unsigned*)&h1;
            w2p[(size_t)r * (NN * HH / 4) + p] = packed;
        }
    }
}

// ---- 2. layer-1 scatter, 2 edges/thread; fp16 row gather (one LDG.128 each) ----
__global__ void k_scatter1(const int* __restrict__ edge_index,
                           const int* __restrict__ edge_type) {
    int p = blockIdx.x * blockDim.x + threadIdx.x;
    if (p >= EE / 2) return;
    int2 src = ((const int2*)edge_index)[p];
    int2 tgt = ((const int2*)(edge_index + EE))[p];
    int2 et  = ((const int2*)edge_type)[p];
    float c0 = (float)g_counts[tgt.x * RR + et.x];
    float c1 = (float)g_counts[tgt.y * RR + et.y];
    float n0 = 1.0f / fmaxf(c0, 1.0f);
    float n1 = 1.0f / fmaxf(c1, 1.0f);
    ((float2*)g_norm)[p] = make_float2(n0, n1);
    uint4 ra = *(const uint4*)&g_w1h[(size_t)et.x * (NN * HH) + src.x * HH];
    uint4 rb = *(const uint4*)&g_w1h[(size_t)et.y * (NN * HH) + src.y * HH];
    float2 a0 = __half22float2(*(__half2*)&ra.x);
    float2 a1 = __half22float2(*(__half2*)&ra.y);
    float2 a2 = __half22float2(*(__half2*)&ra.z);
    float2 a3 = __half22float2(*(__half2*)&ra.w);
    float2 b0 = __half22float2(*(__half2*)&rb.x);
    float2 b1 = __half22float2(*(__half2*)&rb.y);
    float2 b2 = __half22float2(*(__half2*)&rb.z);
    float2 b3 = __half22float2(*(__half2*)&rb.w);
    float* d0 = &g_agg1[tgt.x * HH];
    float* d1 = &g_agg1[tgt.y * HH];
    red_add_v4(d0,     n0 * a0.x, n0 * a0.y, n0 * a1.x, n0 * a1.y);
    red_add_v4(d0 + 4, n0 * a2.x, n0 * a2.y, n0 * a3.x, n0 * a3.y);
    red_add_v4(d1,     n1 * b0.x, n1 * b0.y, n1 * b1.x, n1 * b1.y);
    red_add_v4(d1 + 4, n1 * b2.x, n1 * b2.y, n1 * b3.x, n1 * b3.y);
}

// ---- 3. layer-2 scatter: 2 edges/thread, fp16 weights in smem ----
__global__ void k_scatter2(const int* __restrict__ edge_index,
                           const int* __restrict__ edge_type) {
    __shared__ __half2 sw[RR * WPADH];   // 32 x 65 half2 = 8.1 KB
    for (int i = threadIdx.x; i < RR * HH * CC / 2; i += blockDim.x) {
        int r  = i / (HH * CC / 2);
        int p2 = i % (HH * CC / 2);       // pair index: h*8 + c/2
        sw[r * WPADH + p2] = __floats2half2_rn(g_w2[r * HH * CC + p2 * 2],
                                               g_w2[r * HH * CC + p2 * 2 + 1]);
    }
    __syncthreads();
    int p = blockIdx.x * blockDim.x + threadIdx.x;
    if (p >= EE / 2) return;
    int2 src = ((const int2*)edge_index)[p];
    int2 tgt = ((const int2*)(edge_index + EE))[p];
    int2 et  = ((const int2*)edge_type)[p];
    float2 nm = ((const float2*)g_norm)[p];
    float4 xa0 = *(const float4*)&g_agg1[src.x * HH];
    float4 xa1 = *(const float4*)&g_agg1[src.x * HH + 4];
    float4 xb0 = *(const float4*)&g_agg1[src.y * HH];
    float4 xb1 = *(const float4*)&g_agg1[src.y * HH + 4];
    float xva[HH] = {fmaxf(xa0.x,0.f), fmaxf(xa0.y,0.f), fmaxf(xa0.z,0.f), fmaxf(xa0.w,0.f),
                     fmaxf(xa1.x,0.f), fmaxf(xa1.y,0.f), fmaxf(xa1.z,0.f), fmaxf(xa1.w,0.f)};
    float xvb[HH] = {fmaxf(xb0.x,0.f), fmaxf(xb0.y,0.f), fmaxf(xb0.z,0.f), fmaxf(xb0.w,0.f),
                     fmaxf(xb1.x,0.f), fmaxf(xb1.y,0.f), fmaxf(xb1.z,0.f), fmaxf(xb1.w,0.f)};
    const __half2* wa = &sw[et.x * WPADH];
    const __half2* wb = &sw[et.y * WPADH];
    float sa[CC], sb[CC];
#pragma unroll
    for (int c = 0; c < CC; c++) { sa[c] = 0.0f; sb[c] = 0.0f; }
#pragma unroll
    for (int h = 0; h < HH; h++) {
        float xh0 = xva[h], xh1 = xvb[h];
#pragma unroll
        for (int c2 = 0; c2 < CC / 2; c2++) {
            float2 wfa = __half22float2(wa[h * (CC / 2) + c2]);
            float2 wfb = __half22float2(wb[h * (CC / 2) + c2]);
            sa[c2 * 2]     += xh0 * wfa.x;
            sa[c2 * 2 + 1] += xh0 * wfa.y;
            sb[c2 * 2]     += xh1 * wfb.x;
            sb[c2 * 2 + 1] += xh1 * wfb.y;
        }
    }
    float* d0 = &g_agg2[tgt.x * CC];
    float* d1 = &g_agg2[tgt.y * CC];
#pragma unroll
    for (int c = 0; c < CC; c += 4)
        red_add_v4(d0 + c, nm.x * sa[c], nm.x * sa[c + 1],
                           nm.x * sa[c + 2], nm.x * sa[c + 3]);
#pragma unroll
    for (int c = 0; c < CC; c += 4)
        red_add_v4(d1 + c, nm.y * sb[c], nm.y * sb[c + 1],
                           nm.y * sb[c + 2], nm.y * sb[c + 3]);
}

// ---- 4. out = log_softmax(agg2 + relu(agg1) @ root2 + bias2) ----
__global__ void k_final(const float* __restrict__ root2,
                        const float* __restrict__ bias2,
                        float* __restrict__ out) {
    __shared__ float sr[HH * CC];
    __shared__ float sb[CC];
    for (int i = threadIdx.x; i < HH * CC; i += blockDim.x) sr[i] = root2[i];
    if (threadIdx.x < CC) sb[threadIdx.x] = bias2[threadIdx.x];
    __syncthreads();
    int n = blockIdx.x * blockDim.x + threadIdx.x;
    if (n >= NN) return;
    float4 x0 = *(const float4*)&g_agg1[n * HH];
    float4 x1 = *(const float4*)&g_agg1[n * HH + 4];
    float xv[HH] = {fmaxf(x0.x,0.f), fmaxf(x0.y,0.f), fmaxf(x0.z,0.f), fmaxf(x0.w,0.f),
                    fmaxf(x1.x,0.f), fmaxf(x1.y,0.f), fmaxf(x1.z,0.f), fmaxf(x1.w,0.f)};
    float v[CC];
    float m = -INFINITY;
#pragma unroll
    for (int c = 0; c < CC; c++) {
        float s = g_agg2[n * CC + c] + sb[c];
#pragma unroll
        for (int h = 0; h < HH; h++) s += xv[h] * sr[h * CC + c];
        v[c] = s;
        m = fmaxf(m, s);
    }
    float sum = 0.0f;
#pragma unroll
    for (int c = 0; c < CC; c++) sum += __expf(v[c] - m);
    float lse = m + __logf(sum);
#pragma unroll
    for (int c = 0; c < CC; c++) out[n * CC + c] = v[c] - lse;
}

extern "C" void kernel_launch(void* const* d_in, const int* in_sizes, int n_in,
                              void* d_out, int out_size) {
    const int*   edge_index = (const int*)d_in[0];   // (2, E)
    const int*   edge_type  = (const int*)d_in[1];   // (E,)
    const float* basis1     = (const float*)d_in[2]; // (B, N, H)
    const float* comp1      = (const float*)d_in[3]; // (R, B)
    const float* root1      = (const float*)d_in[4]; // (N, H)
    const float* bias1      = (const float*)d_in[5]; // (H,)
    const float* basis2     = (const float*)d_in[6]; // (B, H, C)
    const float* comp2      = (const float*)d_in[7]; // (R, B)
    const float* root2      = (const float*)d_in[8]; // (H, C)
    const float* bias2      = (const float*)d_in[9]; // (C,)
    float* out = (float*)d_out;

    k_setup<<<2048, 256>>>(basis2, comp2, root1, bias1);               // idx 0
    k_cw1<<<(EE / 2 + 255) / 256, 256>>>(edge_index, edge_type,
                                         basis1, comp1);               // idx 1
    k_scatter1<<<(EE / 2 + 255) / 256, 256>>>(edge_index, edge_type);  // idx 2
    k_scatter2<<<(EE / 2 + 511) / 512, 512>>>(edge_index, edge_type);  // idx 3 (profiled)
    k_final<<<(NN + 127) / 128, 128>>>(root2, bias2, out);             // idx 4
}